// round 16
// baseline (speedup 1.0000x reference)
#include <cuda_runtime.h>

#define NB 4096
#define NEG 0.02f
// (1/sqrt(5)) * log2(e)
#define CEXP 0.6451928329f

typedef unsigned long long u64;

// hop-2 output: [B*N1, 30]
__device__ float g_h1[NB * 16 * 30];

// ---------------------------------------------------------------------------
__device__ __forceinline__ u64 pk2(float lo, float hi) {
    u64 v; asm("mov.b64 %0,{%1,%2};" : "=l"(v) : "f"(lo), "f"(hi)); return v;
}
__device__ __forceinline__ float2 upk2(u64 v) {
    float2 r; asm("mov.b64 {%0,%1},%2;" : "=f"(r.x), "=f"(r.y) : "l"(v)); return r;
}
__device__ __forceinline__ u64 f2fma(u64 a, u64 b, u64 c) {
    u64 d; asm("fma.rn.f32x2 %0,%1,%2,%3;" : "=l"(d) : "l"(a), "l"(b), "l"(c));
    return d;
}
__device__ __forceinline__ u64 f2add(u64 a, u64 b) {
    u64 d; asm("add.rn.f32x2 %0,%1,%2;" : "=l"(d) : "l"(a), "l"(b));
    return d;
}
__device__ __forceinline__ float ex2f(float x) {
    float r; asm("ex2.approx.f32 %0,%1;" : "=f"(r) : "f"(x)); return r;
}
__device__ __forceinline__ float rcpf(float x) {
    float r; asm("rcp.approx.f32 %0,%1;" : "=f"(r) : "f"(x)); return r;
}

// packed dot, 4 accumulators: 32-float weight row (pad zeroed) vs 16 u64
__device__ __forceinline__ float dotp(const float* __restrict__ wrow,
                                      const u64 (&v)[16]) {
    const ulonglong2* w2 = (const ulonglong2*)wrow;
    u64 a0 = 0ull, a1 = 0ull, a2 = 0ull, a3 = 0ull;
#pragma unroll
    for (int kk = 0; kk < 2; kk++) {
        ulonglong2 wa = w2[4 * kk + 0];
        ulonglong2 wb = w2[4 * kk + 1];
        ulonglong2 wc = w2[4 * kk + 2];
        ulonglong2 wd = w2[4 * kk + 3];
        a0 = f2fma(wa.x, v[8 * kk + 0], a0);
        a1 = f2fma(wa.y, v[8 * kk + 1], a1);
        a2 = f2fma(wb.x, v[8 * kk + 2], a2);
        a3 = f2fma(wb.y, v[8 * kk + 3], a3);
        a0 = f2fma(wc.x, v[8 * kk + 4], a0);
        a1 = f2fma(wc.y, v[8 * kk + 5], a1);
        a2 = f2fma(wd.x, v[8 * kk + 6], a2);
        a3 = f2fma(wd.y, v[8 * kk + 7], a3);
    }
    u64 s = f2add(f2add(a0, a1), f2add(a2, a3));
    float2 f = upk2(s);
    return f.x + f.y;
}

// stage1: y = leaky(x @ lw^T + lb) from pre-loaded packed x
__device__ __forceinline__ void stage1_one(const u64 (&xp)[16],
                                           const float* __restrict__ lw_s,
                                           const float* __restrict__ lb_s,
                                           u64 (&yp)[16]) {
#pragma unroll
    for (int jj = 0; jj < 15; jj++) {
        float y0 = lb_s[2 * jj]     + dotp(lw_s + (2 * jj) * 32, xp);
        float y1 = lb_s[2 * jj + 1] + dotp(lw_s + (2 * jj + 1) * 32, xp);
        y0 = fmaxf(y0, NEG * y0);
        y1 = fmaxf(y1, NEG * y1);
        yp[jj] = pk2(y0, y1);
    }
    yp[15] = 0ull;
}

// ---------------------------------------------------------------------------
// sm layout: lw 0..959 | iw 960..3839 | owT 3840..4799 (TRANSPOSED) |
//            lb 4800 | ib 4832 | ob 4928..4959
//            (q-rows of iw and q-bias pre-scaled by CEXP)
// ---------------------------------------------------------------------------
__device__ __forceinline__ void stage_weights(float* sm, int tid, int nthr,
                                              const float* lw, const float* lb,
                                              const float* iw, const float* ib,
                                              const float* ow, const float* ob) {
    for (int i = tid; i < 4800; i += nthr) {
        int row = i >> 5, col = i & 31;
        float v = 0.f;
        if (col < 30) {
            if (row < 30)       v = lw[row * 30 + col];
            else if (row < 120) {
                v = iw[(row - 30) * 30 + col];
                if (row < 60) v *= CEXP;            // fold attn scale into q
            } else                v = ow[col * 30 + (row - 120)];  // owT
        }
        sm[i] = v;
    }
    if (tid < 30) sm[4800 + tid] = lb[tid];
    if (tid < 90) sm[4832 + tid] = (tid < 30) ? ib[tid] * CEXP : ib[tid];
    if (tid < 32) sm[4928 + tid] = (tid < 30) ? ob[tid] : 0.f;
}

// ===========================================================================
// One GraphLayer for one sequence per warp. Per-seq scratch 1952 floats:
//   KA  : ulonglong2[96] [0,384)    (k0..k3) per (head j in group, row t)
//   KV4 : u64[96]        [384,576)  (k4, v4) packed
//   VA  : ulonglong2[96] [576,960)  (v0..v3)
//   OS  : float[32][31]  [960,1952) per-row attention outputs o[30]
// ===========================================================================
#define BUFF 1952

template <int S, bool FULL>
__device__ __forceinline__ float run_layer(int r,
                                           const u64 (&xp)[16],
                                           const float* __restrict__ sm,
                                           float* __restrict__ buf,
                                           float invS) {
    const float* lw_s  = sm;
    const float* iw_s  = sm + 960;
    const float* owT_s = sm + 3840;
    const float* lb_s  = sm + 4800;
    const float* ib_s  = sm + 4832;
    const float* ob_s  = sm + 4928;
    const bool act = FULL || (r < S);

    ulonglong2* KA  = (ulonglong2*)buf;
    u64*        KV4 = (u64*)(buf + 384);
    ulonglong2* VA  = (ulonglong2*)(buf + 576);
    float*      OS  = buf + 960;          // [32][31]

    u64 yp[16];
    if (act) stage1_one(xp, lw_s, lb_s, yp);

    // ---- head groups of 3: qkv -> stage -> attention -> OS ----------------
#pragma unroll 1
    for (int g = 0; g < 2; g++) {
        u64 q01[3], q23[3];
        float q4[3];
        if (act) {
#pragma unroll
            for (int j = 0; j < 3; j++) {
                const int h = g * 3 + j;
                float a0 = ib_s[h * 5 + 0] + dotp(iw_s + (h * 5 + 0) * 32, yp);
                float a1 = ib_s[h * 5 + 1] + dotp(iw_s + (h * 5 + 1) * 32, yp);
                float a2 = ib_s[h * 5 + 2] + dotp(iw_s + (h * 5 + 2) * 32, yp);
                float a3 = ib_s[h * 5 + 3] + dotp(iw_s + (h * 5 + 3) * 32, yp);
                float a4 = ib_s[h * 5 + 4] + dotp(iw_s + (h * 5 + 4) * 32, yp);
                q01[j] = pk2(a0, a1); q23[j] = pk2(a2, a3); q4[j] = a4;

                float k0 = ib_s[30 + h * 5 + 0] + dotp(iw_s + (30 + h * 5 + 0) * 32, yp);
                float k1 = ib_s[30 + h * 5 + 1] + dotp(iw_s + (30 + h * 5 + 1) * 32, yp);
                float k2 = ib_s[30 + h * 5 + 2] + dotp(iw_s + (30 + h * 5 + 2) * 32, yp);
                float k3 = ib_s[30 + h * 5 + 3] + dotp(iw_s + (30 + h * 5 + 3) * 32, yp);
                float k4 = ib_s[30 + h * 5 + 4] + dotp(iw_s + (30 + h * 5 + 4) * 32, yp);
                float v0 = ib_s[60 + h * 5 + 0] + dotp(iw_s + (60 + h * 5 + 0) * 32, yp);
                float v1 = ib_s[60 + h * 5 + 1] + dotp(iw_s + (60 + h * 5 + 1) * 32, yp);
                float v2 = ib_s[60 + h * 5 + 2] + dotp(iw_s + (60 + h * 5 + 2) * 32, yp);
                float v3 = ib_s[60 + h * 5 + 3] + dotp(iw_s + (60 + h * 5 + 3) * 32, yp);
                float v4 = ib_s[60 + h * 5 + 4] + dotp(iw_s + (60 + h * 5 + 4) * 32, yp);

                ulonglong2 kk; kk.x = pk2(k0, k1); kk.y = pk2(k2, k3);
                KA[j * 32 + r]  = kk;
                KV4[j * 32 + r] = pk2(k4, v4);
                ulonglong2 vv; vv.x = pk2(v0, v1); vv.y = pk2(v2, v3);
                VA[j * 32 + r]  = vv;
            }
        }
        __syncwarp();
        if (act) {
            // ---- merged attention: all 3 heads in ONE t-loop (3x ILP) -----
            u64 a01[3] = {0ull, 0ull, 0ull};
            u64 a23[3] = {0ull, 0ull, 0ull};
            float a4[3] = {0.f, 0.f, 0.f};
            float es[3] = {0.f, 0.f, 0.f};
#pragma unroll 4
            for (int t = 0; t < S; t++) {
#pragma unroll
                for (int j = 0; j < 3; j++) {
                    ulonglong2 ka = KA[j * 32 + t];
                    float2 kv4 = upk2(KV4[j * 32 + t]);
                    u64 s2 = f2fma(ka.x, q01[j], f2fma(ka.y, q23[j], 0ull));
                    float2 sp = upk2(s2);
                    float e = ex2f(fmaf(q4[j], kv4.x, sp.x + sp.y));
                    u64 ee = pk2(e, e);
                    ulonglong2 va = VA[j * 32 + t];
                    a01[j] = f2fma(ee, va.x, a01[j]);
                    a23[j] = f2fma(ee, va.y, a23[j]);
                    a4[j]  = fmaf(e, kv4.y, a4[j]);
                    es[j] += e;
                }
            }
#pragma unroll
            for (int j = 0; j < 3; j++) {
                const int h = g * 3 + j;
                float inv = rcpf(es[j]);
                float2 p01 = upk2(a01[j]), p23 = upk2(a23[j]);
                float* os = OS + r * 31 + h * 5;
                os[0] = p01.x * inv;
                os[1] = p01.y * inv;
                os[2] = p23.x * inv;
                os[3] = p23.y * inv;
                os[4] = a4[j] * inv;
            }
        }
        __syncwarp();   // protects K/V rewrite (g=0) and OS-before-mean (g=1)
    }

    // ---- column mean over rows (mean commutes with out-proj) --------------
    float m = 0.f;
    if (r < 30) {
#pragma unroll
        for (int t = 0; t < S; t++) m += OS[t * 31 + r];
        m *= invS;
    }

    // ---- emb = ob + ow @ mean via owT (conflict-free) + shuffle -----------
    float emb = (r < 30) ? ob_s[r] : 0.f;
#pragma unroll
    for (int c = 0; c < 30; c++) {
        float mc = __shfl_sync(0xffffffffu, m, c);
        float wc = owT_s[c * 32 + r];        // lane r -> bank r, no conflict
        emb = fmaf(mc, wc, emb);
    }
    return emb;
}

// ===========================================================================
// hop2: 8 sequences/CTA (one per warp). Coalesced x-preload into smem XS.
// ===========================================================================
#define WPC2 8
#define NSEQ2 (NB * 16)
#define XS_OFF (4960 + WPC2 * BUFF)          // 20576
#define XS_FLOATS (WPC2 * 32 * 30)           // 7680
#define SMEM1_FLOATS (XS_OFF + XS_FLOATS)    // 28256 -> 113,024 B

__global__ void __launch_bounds__(256, 2) hop2_kernel(
    const float* __restrict__ x2,
    const float* __restrict__ lw, const float* __restrict__ lb,
    const float* __restrict__ iw, const float* __restrict__ ib,
    const float* __restrict__ ow, const float* __restrict__ ob) {
    extern __shared__ float sm[];
    const int tid = threadIdx.x;
    stage_weights(sm, tid, 256, lw, lb, iw, ib, ow, ob);

    // ---- coalesced preload of this CTA's 8 sequences (7680 floats) --------
    {
        float4* xs4 = (float4*)(sm + XS_OFF);
        const float4* src = (const float4*)(x2 + (long)blockIdx.x * XS_FLOATS);
        for (int i = tid; i < XS_FLOATS / 4; i += 256) xs4[i] = src[i];
    }
    __syncthreads();

    const int seq = tid >> 5, r = tid & 31;
    const long sg = (long)blockIdx.x * WPC2 + seq;
    float* buf = sm + 4960 + seq * BUFF;

    // packed x from smem (LDS, ~2-way conflict vs ~30-line LDG spread)
    u64 xp[16];
    {
        const float* xrow = sm + XS_OFF + (seq * 32 + r) * 30;
#pragma unroll
        for (int k = 0; k < 15; k++) {
            float2 t = *(const float2*)(xrow + 2 * k);
            xp[k] = pk2(t.x, t.y);
        }
        xp[15] = 0ull;
    }

    float emb = run_layer<32, true>(r, xp, sm, buf, 1.f / 32.f);
    if (r < 30) g_h1[sg * 30 + r] = emb;
}

// ===========================================================================
// hop1: 6 nodes/CTA (192 thr) + classifier MLP + 2-class softmax (guarded).
// ===========================================================================
#define WPC1 6
#define OFF_CW1P (4960 + WPC1 * BUFF)    // 16672
#define OFF_CB1  (OFF_CW1P + 64 * 31)    // 18656
#define OFF_CW2P (OFF_CB1 + 64)          // 18720
#define OFF_CB2  (OFF_CW2P + 64 * 65)    // 22880
#define OFF_CW3  (OFF_CB2 + 64)          // 22944
#define OFF_CB3  (OFF_CW3 + 128)         // 23072
#define OFF_EMB  (OFF_CB3 + 4)           // 23076
#define OFF_HA   (OFF_EMB + WPC1 * 32)   // 23268
#define OFF_HB   (OFF_HA + WPC1 * 64)    // 23652
#define SMEM2_FLOATS (OFF_HB + WPC1 * 64)  // 24036 -> 96,144 B

__global__ void __launch_bounds__(192, 2) hop1_kernel(
    const float* __restrict__ self_feat,
    const float* __restrict__ lw, const float* __restrict__ lb,
    const float* __restrict__ iw, const float* __restrict__ ib,
    const float* __restrict__ ow, const float* __restrict__ ob,
    const float* __restrict__ cw1, const float* __restrict__ cb1,
    const float* __restrict__ cw2, const float* __restrict__ cb2,
    const float* __restrict__ cw3, const float* __restrict__ cb3,
    float* __restrict__ out) {
    extern __shared__ float sm[];
    const int tid = threadIdx.x;
    stage_weights(sm, tid, 192, lw, lb, iw, ib, ow, ob);
    float* cw1p = sm + OFF_CW1P;
    float* cb1s = sm + OFF_CB1;
    float* cw2p = sm + OFF_CW2P;
    float* cb2s = sm + OFF_CB2;
    float* cw3s = sm + OFF_CW3;
    float* cb3s = sm + OFF_CB3;
    float* embS = sm + OFF_EMB;
    float* hA   = sm + OFF_HA;
    float* hB   = sm + OFF_HB;
    for (int i = tid; i < 64 * 31; i += 192) {
        int row = i / 31, c = i % 31;
        cw1p[i] = (c < 30) ? cw1[row * 30 + c] : 0.f;
    }
    for (int i = tid; i < 64 * 65; i += 192) {
        int row = i / 65, c = i % 65;
        cw2p[i] = (c < 64) ? cw2[row * 64 + c] : 0.f;
    }
    if (tid < 64)  { cb1s[tid] = cb1[tid]; cb2s[tid] = cb2[tid]; }
    if (tid < 128) cw3s[tid] = cw3[tid];
    if (tid < 2)   cb3s[tid] = cb3[tid];
    __syncthreads();

    const int seq = tid >> 5, r = tid & 31;
    const int b = blockIdx.x * WPC1 + seq;
    if (b >= NB) return;
    float* buf = sm + 4960 + seq * BUFF;

    u64 xp[16];
    if (r < 17) {
        const float* xrow = (r < 16) ? (g_h1 + ((long)b * 16 + r) * 30)
                                     : (self_feat + (long)b * 30);
#pragma unroll
        for (int k = 0; k < 15; k++) {
            float2 t = *(const float2*)(xrow + 2 * k);
            xp[k] = pk2(t.x, t.y);
        }
    } else {
#pragma unroll
        for (int k = 0; k < 15; k++) xp[k] = 0ull;
    }
    xp[15] = 0ull;

    float m = run_layer<17, false>(r, xp, sm, buf, 1.f / 17.f);
    if (r < 30) embS[seq * 32 + r] = m;
    __syncwarp();

    // ---- classifier MLP (per warp) ----------------------------------------
    const float* emb = embS + seq * 32;
#pragma unroll
    for (int half = 0; half < 2; half++) {
        int j = r + 32 * half;
        float acc = cb1s[j];
#pragma unroll
        for (int k = 0; k < 30; k++) acc += emb[k] * cw1p[j * 31 + k];
        hA[seq * 64 + j] = fmaxf(acc, NEG * acc);
    }
    __syncwarp();
#pragma unroll
    for (int half = 0; half < 2; half++) {
        int j = r + 32 * half;
        float acc = cb2s[j];
#pragma unroll
        for (int k = 0; k < 64; k++) acc += hA[seq * 64 + k] * cw2p[j * 65 + k];
        hB[seq * 64 + j] = fmaxf(acc, NEG * acc);
    }
    __syncwarp();
    if (r < 2) {
        float acc = cb3s[r];
#pragma unroll
        for (int k = 0; k < 64; k++) acc += hB[seq * 64 + k] * cw3s[r * 64 + k];
        embS[seq * 32 + 30 + r] = acc;
    }
    __syncwarp();
    if (r == 0) {
        float l0 = embS[seq * 32 + 30], l1 = embS[seq * 32 + 31];
        float mx = fmaxf(l0, l1);
        float e0 = __expf(l0 - mx), e1 = __expf(l1 - mx);
        float inv = 1.f / (e0 + e1);
        out[(long)b * 2 + 0] = e0 * inv;
        out[(long)b * 2 + 1] = e1 * inv;
    }
}

// ===========================================================================
extern "C" void kernel_launch(void* const* d_in, const int* in_sizes, int n_in,
                              void* d_out, int out_size) {
    const float* x2   = (const float*)d_in[0];
    const float* self = (const float*)d_in[1];
    const float* lw2  = (const float*)d_in[2];
    const float* lb2  = (const float*)d_in[3];
    const float* iw2  = (const float*)d_in[4];
    const float* ib2  = (const float*)d_in[5];
    const float* ow2  = (const float*)d_in[6];
    const float* ob2  = (const float*)d_in[7];
    const float* lw1  = (const float*)d_in[8];
    const float* lb1  = (const float*)d_in[9];
    const float* iw1  = (const float*)d_in[10];
    const float* ib1  = (const float*)d_in[11];
    const float* ow1  = (const float*)d_in[12];
    const float* ob1  = (const float*)d_in[13];
    const float* cw1  = (const float*)d_in[14];
    const float* cb1  = (const float*)d_in[15];
    const float* cw2  = (const float*)d_in[16];
    const float* cb2  = (const float*)d_in[17];
    const float* cw3  = (const float*)d_in[18];
    const float* cb3  = (const float*)d_in[19];
    float* out = (float*)d_out;

    const int smem1 = SMEM1_FLOATS * 4;
    const int smem2 = SMEM2_FLOATS * 4;
    cudaFuncSetAttribute(hop2_kernel,
                         cudaFuncAttributeMaxDynamicSharedMemorySize, smem1);
    cudaFuncSetAttribute(hop1_kernel,
                         cudaFuncAttributeMaxDynamicSharedMemorySize, smem2);

    hop2_kernel<<<NSEQ2 / WPC2, 256, smem1>>>(x2, lw2, lb2, iw2, ib2, ow2, ob2);
    hop1_kernel<<<(NB + WPC1 - 1) / WPC1, 192, smem2>>>(
        self, lw1, lb1, iw1, ib1, ow1, ob1,
        cw1, cb1, cw2, cb2, cw3, cb3, out);
}

// round 17
// speedup vs baseline: 1.0123x; 1.0123x over previous
#include <cuda_runtime.h>

#define NB 4096
#define NEG 0.02f
// (1/sqrt(5)) * log2(e)
#define CEXP 0.6451928329f

typedef unsigned long long u64;

// hop-2 output: [B*N1, 30]
__device__ float g_h1[NB * 16 * 30];

// ---------------------------------------------------------------------------
__device__ __forceinline__ u64 pk2(float lo, float hi) {
    u64 v; asm("mov.b64 %0,{%1,%2};" : "=l"(v) : "f"(lo), "f"(hi)); return v;
}
__device__ __forceinline__ float2 upk2(u64 v) {
    float2 r; asm("mov.b64 {%0,%1},%2;" : "=f"(r.x), "=f"(r.y) : "l"(v)); return r;
}
__device__ __forceinline__ u64 f2fma(u64 a, u64 b, u64 c) {
    u64 d; asm("fma.rn.f32x2 %0,%1,%2,%3;" : "=l"(d) : "l"(a), "l"(b), "l"(c));
    return d;
}
__device__ __forceinline__ u64 f2add(u64 a, u64 b) {
    u64 d; asm("add.rn.f32x2 %0,%1,%2;" : "=l"(d) : "l"(a), "l"(b));
    return d;
}
__device__ __forceinline__ float ex2f(float x) {
    float r; asm("ex2.approx.f32 %0,%1;" : "=f"(r) : "f"(x)); return r;
}
__device__ __forceinline__ float rcpf(float x) {
    float r; asm("rcp.approx.f32 %0,%1;" : "=f"(r) : "f"(x)); return r;
}

// packed dot, 4 accumulators: 32-float weight row (pad zeroed) vs 16 u64
__device__ __forceinline__ float dotp(const float* __restrict__ wrow,
                                      const u64 (&v)[16]) {
    const ulonglong2* w2 = (const ulonglong2*)wrow;
    u64 a0 = 0ull, a1 = 0ull, a2 = 0ull, a3 = 0ull;
#pragma unroll
    for (int kk = 0; kk < 2; kk++) {
        ulonglong2 wa = w2[4 * kk + 0];
        ulonglong2 wb = w2[4 * kk + 1];
        ulonglong2 wc = w2[4 * kk + 2];
        ulonglong2 wd = w2[4 * kk + 3];
        a0 = f2fma(wa.x, v[8 * kk + 0], a0);
        a1 = f2fma(wa.y, v[8 * kk + 1], a1);
        a2 = f2fma(wb.x, v[8 * kk + 2], a2);
        a3 = f2fma(wb.y, v[8 * kk + 3], a3);
        a0 = f2fma(wc.x, v[8 * kk + 4], a0);
        a1 = f2fma(wc.y, v[8 * kk + 5], a1);
        a2 = f2fma(wd.x, v[8 * kk + 6], a2);
        a3 = f2fma(wd.y, v[8 * kk + 7], a3);
    }
    u64 s = f2add(f2add(a0, a1), f2add(a2, a3));
    float2 f = upk2(s);
    return f.x + f.y;
}

// stage1: y = leaky(x @ lw^T + lb) from pre-loaded packed x
__device__ __forceinline__ void stage1_one(const u64 (&xp)[16],
                                           const float* __restrict__ lw_s,
                                           const float* __restrict__ lb_s,
                                           u64 (&yp)[16]) {
#pragma unroll
    for (int jj = 0; jj < 15; jj++) {
        float y0 = lb_s[2 * jj]     + dotp(lw_s + (2 * jj) * 32, xp);
        float y1 = lb_s[2 * jj + 1] + dotp(lw_s + (2 * jj + 1) * 32, xp);
        y0 = fmaxf(y0, NEG * y0);
        y1 = fmaxf(y1, NEG * y1);
        yp[jj] = pk2(y0, y1);
    }
    yp[15] = 0ull;
}

// ---------------------------------------------------------------------------
// sm layout: lw 0..959 | iw 960..3839 | owT 3840..4799 (TRANSPOSED) |
//            lb 4800 | ib 4832 | ob 4928..4959
//            (q-rows of iw and q-bias pre-scaled by CEXP)
// ---------------------------------------------------------------------------
__device__ __forceinline__ void stage_weights(float* sm, int tid, int nthr,
                                              const float* lw, const float* lb,
                                              const float* iw, const float* ib,
                                              const float* ow, const float* ob) {
    for (int i = tid; i < 4800; i += nthr) {
        int row = i >> 5, col = i & 31;
        float v = 0.f;
        if (col < 30) {
            if (row < 30)       v = lw[row * 30 + col];
            else if (row < 120) {
                v = iw[(row - 30) * 30 + col];
                if (row < 60) v *= CEXP;            // fold attn scale into q
            } else                v = ow[col * 30 + (row - 120)];  // owT
        }
        sm[i] = v;
    }
    if (tid < 30) sm[4800 + tid] = lb[tid];
    if (tid < 90) sm[4832 + tid] = (tid < 30) ? ib[tid] * CEXP : ib[tid];
    if (tid < 32) sm[4928 + tid] = (tid < 30) ? ob[tid] : 0.f;
}

// ===========================================================================
// One GraphLayer for one sequence per warp. Per-seq scratch 1952 floats:
//   KA  : ulonglong2[96] [0,384)    (k0..k3) per (head j in group, row t)
//   KV4 : u64[96]        [384,576)  (k4, v4) packed
//   VA  : ulonglong2[96] [576,960)  (v0..v3)
//   OS  : float[32][31]  [960,1952) per-row attention outputs o[30]
// ===========================================================================
#define BUFF 1952

template <int S, bool FULL>
__device__ __forceinline__ float run_layer(int r,
                                           const u64 (&xp)[16],
                                           const float* __restrict__ sm,
                                           float* __restrict__ buf,
                                           float invS) {
    const float* lw_s  = sm;
    const float* iw_s  = sm + 960;
    const float* owT_s = sm + 3840;
    const float* lb_s  = sm + 4800;
    const float* ib_s  = sm + 4832;
    const float* ob_s  = sm + 4928;
    const bool act = FULL || (r < S);

    ulonglong2* KA  = (ulonglong2*)buf;
    u64*        KV4 = (u64*)(buf + 384);
    ulonglong2* VA  = (ulonglong2*)(buf + 576);
    float*      OS  = buf + 960;          // [32][31]

    u64 yp[16];
    if (act) stage1_one(xp, lw_s, lb_s, yp);

    // ---- head groups of 3: qkv -> stage -> attention -> OS ----------------
#pragma unroll 1
    for (int g = 0; g < 2; g++) {
        u64 q01[3], q23[3];
        float q4[3];
        if (act) {
#pragma unroll
            for (int j = 0; j < 3; j++) {
                const int h = g * 3 + j;
                float a0 = ib_s[h * 5 + 0] + dotp(iw_s + (h * 5 + 0) * 32, yp);
                float a1 = ib_s[h * 5 + 1] + dotp(iw_s + (h * 5 + 1) * 32, yp);
                float a2 = ib_s[h * 5 + 2] + dotp(iw_s + (h * 5 + 2) * 32, yp);
                float a3 = ib_s[h * 5 + 3] + dotp(iw_s + (h * 5 + 3) * 32, yp);
                float a4 = ib_s[h * 5 + 4] + dotp(iw_s + (h * 5 + 4) * 32, yp);
                q01[j] = pk2(a0, a1); q23[j] = pk2(a2, a3); q4[j] = a4;

                float k0 = ib_s[30 + h * 5 + 0] + dotp(iw_s + (30 + h * 5 + 0) * 32, yp);
                float k1 = ib_s[30 + h * 5 + 1] + dotp(iw_s + (30 + h * 5 + 1) * 32, yp);
                float k2 = ib_s[30 + h * 5 + 2] + dotp(iw_s + (30 + h * 5 + 2) * 32, yp);
                float k3 = ib_s[30 + h * 5 + 3] + dotp(iw_s + (30 + h * 5 + 3) * 32, yp);
                float k4 = ib_s[30 + h * 5 + 4] + dotp(iw_s + (30 + h * 5 + 4) * 32, yp);
                float v0 = ib_s[60 + h * 5 + 0] + dotp(iw_s + (60 + h * 5 + 0) * 32, yp);
                float v1 = ib_s[60 + h * 5 + 1] + dotp(iw_s + (60 + h * 5 + 1) * 32, yp);
                float v2 = ib_s[60 + h * 5 + 2] + dotp(iw_s + (60 + h * 5 + 2) * 32, yp);
                float v3 = ib_s[60 + h * 5 + 3] + dotp(iw_s + (60 + h * 5 + 3) * 32, yp);
                float v4 = ib_s[60 + h * 5 + 4] + dotp(iw_s + (60 + h * 5 + 4) * 32, yp);

                ulonglong2 kk; kk.x = pk2(k0, k1); kk.y = pk2(k2, k3);
                KA[j * 32 + r]  = kk;
                KV4[j * 32 + r] = pk2(k4, v4);
                ulonglong2 vv; vv.x = pk2(v0, v1); vv.y = pk2(v2, v3);
                VA[j * 32 + r]  = vv;
            }
        }
        __syncwarp();
        if (act) {
            // ---- merged attention: all 3 heads in ONE t-loop (3x ILP) -----
            u64 a01[3] = {0ull, 0ull, 0ull};
            u64 a23[3] = {0ull, 0ull, 0ull};
            float a4[3] = {0.f, 0.f, 0.f};
            float es[3] = {0.f, 0.f, 0.f};
#pragma unroll 4
            for (int t = 0; t < S; t++) {
#pragma unroll
                for (int j = 0; j < 3; j++) {
                    ulonglong2 ka = KA[j * 32 + t];
                    float2 kv4 = upk2(KV4[j * 32 + t]);
                    u64 s2 = f2fma(ka.x, q01[j], f2fma(ka.y, q23[j], 0ull));
                    float2 sp = upk2(s2);
                    float e = ex2f(fmaf(q4[j], kv4.x, sp.x + sp.y));
                    u64 ee = pk2(e, e);
                    ulonglong2 va = VA[j * 32 + t];
                    a01[j] = f2fma(ee, va.x, a01[j]);
                    a23[j] = f2fma(ee, va.y, a23[j]);
                    a4[j]  = fmaf(e, kv4.y, a4[j]);
                    es[j] += e;
                }
            }
#pragma unroll
            for (int j = 0; j < 3; j++) {
                const int h = g * 3 + j;
                float inv = rcpf(es[j]);
                float2 p01 = upk2(a01[j]), p23 = upk2(a23[j]);
                float* os = OS + r * 31 + h * 5;
                os[0] = p01.x * inv;
                os[1] = p01.y * inv;
                os[2] = p23.x * inv;
                os[3] = p23.y * inv;
                os[4] = a4[j] * inv;
            }
        }
        __syncwarp();   // protects K/V rewrite (g=0) and OS-before-mean (g=1)
    }

    // ---- column mean over rows (mean commutes with out-proj) --------------
    float m = 0.f;
    if (r < 30) {
#pragma unroll
        for (int t = 0; t < S; t++) m += OS[t * 31 + r];
        m *= invS;
    }

    // ---- emb = ob + ow @ mean via owT (conflict-free) + shuffle -----------
    float emb = (r < 30) ? ob_s[r] : 0.f;
#pragma unroll
    for (int c = 0; c < 30; c++) {
        float mc = __shfl_sync(0xffffffffu, m, c);
        float wc = owT_s[c * 32 + r];        // lane r -> bank r, no conflict
        emb = fmaf(mc, wc, emb);
    }
    return emb;
}

// ===========================================================================
// hop2: 8 sequences/CTA (one per warp), x loaded direct from global (R15).
// ===========================================================================
#define WPC2 8
#define NSEQ2 (NB * 16)
#define SMEM1_FLOATS (4960 + WPC2 * BUFF)    // 20576 -> 82,304 B

__global__ void __launch_bounds__(256, 2) hop2_kernel(
    const float* __restrict__ x2,
    const float* __restrict__ lw, const float* __restrict__ lb,
    const float* __restrict__ iw, const float* __restrict__ ib,
    const float* __restrict__ ow, const float* __restrict__ ob) {
    extern __shared__ float sm[];
    const int tid = threadIdx.x;
    stage_weights(sm, tid, 256, lw, lb, iw, ib, ow, ob);
    __syncthreads();

    const int seq = tid >> 5, r = tid & 31;
    const long sg = (long)blockIdx.x * WPC2 + seq;
    float* buf = sm + 4960 + seq * BUFF;

    u64 xp[16];
    {
        const float* xrow = x2 + (sg * 32 + r) * 30;
#pragma unroll
        for (int k = 0; k < 15; k++) {
            float2 t = *(const float2*)(xrow + 2 * k);
            xp[k] = pk2(t.x, t.y);
        }
        xp[15] = 0ull;
    }

    float emb = run_layer<32, true>(r, xp, sm, buf, 1.f / 32.f);
    if (r < 30) g_h1[sg * 30 + r] = emb;
}

// ===========================================================================
// hop1: 8 nodes/CTA (256 thr, (256,2) -> 16 warps/SM) + classifier MLP.
// Grid 512 exact (4096/8).
// ===========================================================================
#define WPC1 8
#define OFF_CW1P (4960 + WPC1 * BUFF)    // 20576
#define OFF_CB1  (OFF_CW1P + 64 * 31)    // 22560
#define OFF_CW2P (OFF_CB1 + 64)          // 22624
#define OFF_CB2  (OFF_CW2P + 64 * 65)    // 26784
#define OFF_CW3  (OFF_CB2 + 64)          // 26848
#define OFF_CB3  (OFF_CW3 + 128)         // 26976
#define OFF_EMB  (OFF_CB3 + 4)           // 26980
#define OFF_HA   (OFF_EMB + WPC1 * 32)   // 27236
#define OFF_HB   (OFF_HA + WPC1 * 64)    // 27748
#define SMEM2_FLOATS (OFF_HB + WPC1 * 64)  // 28260 -> 113,040 B

__global__ void __launch_bounds__(256, 2) hop1_kernel(
    const float* __restrict__ self_feat,
    const float* __restrict__ lw, const float* __restrict__ lb,
    const float* __restrict__ iw, const float* __restrict__ ib,
    const float* __restrict__ ow, const float* __restrict__ ob,
    const float* __restrict__ cw1, const float* __restrict__ cb1,
    const float* __restrict__ cw2, const float* __restrict__ cb2,
    const float* __restrict__ cw3, const float* __restrict__ cb3,
    float* __restrict__ out) {
    extern __shared__ float sm[];
    const int tid = threadIdx.x;
    stage_weights(sm, tid, 256, lw, lb, iw, ib, ow, ob);
    float* cw1p = sm + OFF_CW1P;
    float* cb1s = sm + OFF_CB1;
    float* cw2p = sm + OFF_CW2P;
    float* cb2s = sm + OFF_CB2;
    float* cw3s = sm + OFF_CW3;
    float* cb3s = sm + OFF_CB3;
    float* embS = sm + OFF_EMB;
    float* hA   = sm + OFF_HA;
    float* hB   = sm + OFF_HB;
    for (int i = tid; i < 64 * 31; i += 256) {
        int row = i / 31, c = i % 31;
        cw1p[i] = (c < 30) ? cw1[row * 30 + c] : 0.f;
    }
    for (int i = tid; i < 64 * 65; i += 256) {
        int row = i / 65, c = i % 65;
        cw2p[i] = (c < 64) ? cw2[row * 64 + c] : 0.f;
    }
    if (tid < 64)  { cb1s[tid] = cb1[tid]; cb2s[tid] = cb2[tid]; }
    if (tid < 128) cw3s[tid] = cw3[tid];
    if (tid < 2)   cb3s[tid] = cb3[tid];
    __syncthreads();

    const int seq = tid >> 5, r = tid & 31;
    const int b = blockIdx.x * WPC1 + seq;
    float* buf = sm + 4960 + seq * BUFF;

    u64 xp[16];
    if (r < 17) {
        const float* xrow = (r < 16) ? (g_h1 + ((long)b * 16 + r) * 30)
                                     : (self_feat + (long)b * 30);
#pragma unroll
        for (int k = 0; k < 15; k++) {
            float2 t = *(const float2*)(xrow + 2 * k);
            xp[k] = pk2(t.x, t.y);
        }
    } else {
#pragma unroll
        for (int k = 0; k < 15; k++) xp[k] = 0ull;
    }
    xp[15] = 0ull;

    float m = run_layer<17, false>(r, xp, sm, buf, 1.f / 17.f);
    if (r < 30) embS[seq * 32 + r] = m;
    __syncwarp();

    // ---- classifier MLP (per warp) ----------------------------------------
    const float* emb = embS + seq * 32;
#pragma unroll
    for (int half = 0; half < 2; half++) {
        int j = r + 32 * half;
        float acc = cb1s[j];
#pragma unroll
        for (int k = 0; k < 30; k++) acc += emb[k] * cw1p[j * 31 + k];
        hA[seq * 64 + j] = fmaxf(acc, NEG * acc);
    }
    __syncwarp();
#pragma unroll
    for (int half = 0; half < 2; half++) {
        int j = r + 32 * half;
        float acc = cb2s[j];
#pragma unroll
        for (int k = 0; k < 64; k++) acc += hA[seq * 64 + k] * cw2p[j * 65 + k];
        hB[seq * 64 + j] = fmaxf(acc, NEG * acc);
    }
    __syncwarp();
    if (r < 2) {
        float acc = cb3s[r];
#pragma unroll
        for (int k = 0; k < 64; k++) acc += hB[seq * 64 + k] * cw3s[r * 64 + k];
        embS[seq * 32 + 30 + r] = acc;
    }
    __syncwarp();
    if (r == 0) {
        float l0 = embS[seq * 32 + 30], l1 = embS[seq * 32 + 31];
        float mx = fmaxf(l0, l1);
        float e0 = __expf(l0 - mx), e1 = __expf(l1 - mx);
        float inv = 1.f / (e0 + e1);
        out[(long)b * 2 + 0] = e0 * inv;
        out[(long)b * 2 + 1] = e1 * inv;
    }
}

// ===========================================================================
extern "C" void kernel_launch(void* const* d_in, const int* in_sizes, int n_in,
                              void* d_out, int out_size) {
    const float* x2   = (const float*)d_in[0];
    const float* self = (const float*)d_in[1];
    const float* lw2  = (const float*)d_in[2];
    const float* lb2  = (const float*)d_in[3];
    const float* iw2  = (const float*)d_in[4];
    const float* ib2  = (const float*)d_in[5];
    const float* ow2  = (const float*)d_in[6];
    const float* ob2  = (const float*)d_in[7];
    const float* lw1  = (const float*)d_in[8];
    const float* lb1  = (const float*)d_in[9];
    const float* iw1  = (const float*)d_in[10];
    const float* ib1  = (const float*)d_in[11];
    const float* ow1  = (const float*)d_in[12];
    const float* ob1  = (const float*)d_in[13];
    const float* cw1  = (const float*)d_in[14];
    const float* cb1  = (const float*)d_in[15];
    const float* cw2  = (const float*)d_in[16];
    const float* cb2  = (const float*)d_in[17];
    const float* cw3  = (const float*)d_in[18];
    const float* cb3  = (const float*)d_in[19];
    float* out = (float*)d_out;

    const int smem1 = SMEM1_FLOATS * 4;
    const int smem2 = SMEM2_FLOATS * 4;
    cudaFuncSetAttribute(hop2_kernel,
                         cudaFuncAttributeMaxDynamicSharedMemorySize, smem1);
    cudaFuncSetAttribute(hop1_kernel,
                         cudaFuncAttributeMaxDynamicSharedMemorySize, smem2);

    hop2_kernel<<<NSEQ2 / WPC2, 256, smem1>>>(x2, lw2, lb2, iw2, ib2, ow2, ob2);
    hop1_kernel<<<NB / WPC1, 256, smem2>>>(self, lw1, lb1, iw1, ib1, ow1, ob1,
                                           cw1, cb1, cw2, cb2, cw3, cb3, out);
}